// round 8
// baseline (speedup 1.0000x reference)
#include <cuda_runtime.h>
#include <cuda_fp16.h>
#include <math.h>
#include <stdint.h>

#define Bz 4
#define Tz 2048
#define Cz 1024
#define Hz 16
#define HDz 64
#define Mz (Bz * Tz)

#define QSCALE 0.1803368801111204f   // 1/sqrt(64) * log2(e)

// ---------------- scratch ----------------------------------------------------
__device__ __half g_qh[(size_t)Bz * Hz * Tz * HDz];
__device__ __half g_kh[(size_t)Bz * Hz * Tz * HDz];
__device__ __half g_vh[(size_t)Bz * Hz * Tz * HDz];
__device__ __half g_xh[(size_t)Mz * Cz];
__device__ __half g_wat[(size_t)3 * Cz * Cz];
__device__ __half g_wpt[(size_t)Cz * Cz];
__device__ __half g_att_h[(size_t)Mz * Cz];

// ---------------- helpers ----------------------------------------------------
static __device__ __forceinline__ uint32_t s2u(const void* p) {
    uint32_t a;
    asm("{ .reg .u64 t; cvta.to.shared.u64 t, %1; cvt.u32.u64 %0, t; }"
        : "=r"(a) : "l"(p));
    return a;
}

static __device__ __forceinline__ void cpa16(uint32_t dst, const void* src) {
    asm volatile("cp.async.cg.shared.global [%0], [%1], 16;"
                 :: "r"(dst), "l"(__cvta_generic_to_global(src)));
}

static __device__ __forceinline__ void ldm4(uint32_t* r, uint32_t addr) {
    asm volatile("ldmatrix.sync.aligned.m8n8.x4.shared.b16 {%0,%1,%2,%3}, [%4];"
                 : "=r"(r[0]), "=r"(r[1]), "=r"(r[2]), "=r"(r[3]) : "r"(addr));
}

static __device__ __forceinline__ void ldm4t(uint32_t* r, uint32_t addr) {
    asm volatile("ldmatrix.sync.aligned.m8n8.x4.trans.shared.b16 {%0,%1,%2,%3}, [%4];"
                 : "=r"(r[0]), "=r"(r[1]), "=r"(r[2]), "=r"(r[3]) : "r"(addr));
}

static __device__ __forceinline__ void mma16816(float* c, const uint32_t* a,
                                                const uint32_t* b) {
    asm volatile(
        "mma.sync.aligned.m16n8k16.row.col.f32.f16.f16.f32 "
        "{%0,%1,%2,%3}, {%4,%5,%6,%7}, {%8,%9}, {%0,%1,%2,%3};"
        : "+f"(c[0]), "+f"(c[1]), "+f"(c[2]), "+f"(c[3])
        : "r"(a[0]), "r"(a[1]), "r"(a[2]), "r"(a[3]), "r"(b[0]), "r"(b[1]));
}

static __device__ __forceinline__ float ex2f(float x) {
    float y;
    asm("ex2.approx.ftz.f32 %0, %1;" : "=f"(y) : "f"(x));
    return y;
}

// ---------------- conversion kernels ----------------------------------------
__global__ void conv_x_kernel(const float4* __restrict__ x, uint2* __restrict__ xh, int n4) {
    int i = blockIdx.x * blockDim.x + threadIdx.x;
    if (i < n4) {
        float4 v = x[i];
        __half2 h0 = __floats2half2_rn(v.x, v.y);
        __half2 h1 = __floats2half2_rn(v.z, v.w);
        uint2 u;
        u.x = *reinterpret_cast<uint32_t*>(&h0);
        u.y = *reinterpret_cast<uint32_t*>(&h1);
        xh[i] = u;
    }
}

__global__ void convT_kernel(const float* __restrict__ W, __half* __restrict__ Wt,
                             int R, int C) {
    __shared__ float t[32][33];
    int c0 = blockIdx.x * 32, r0 = blockIdx.y * 32;
    int tx = threadIdx.x, ty = threadIdx.y;
#pragma unroll
    for (int i = 0; i < 4; i++)
        t[ty + i * 8][tx] = W[(size_t)(r0 + ty + i * 8) * C + c0 + tx];
    __syncthreads();
#pragma unroll
    for (int i = 0; i < 4; i++)
        Wt[(size_t)(c0 + ty + i * 8) * R + r0 + tx] = __float2half_rn(t[tx][ty + i * 8]);
}

// ---------------- mma.sync fp16 GEMM: CTA 128x256, 8 warps of 64x64 -----------
// D = A[M,1024] @ B[N,1024]^T.  chunk=32, NSTAGE=4, 256 threads, 1 CTA/SM.
#define NSTAGE 4
#define A_B 10240              // A stage bytes (128 rows x 80B)
#define B_B 20480              // B stage bytes (256 rows x 80B)
#define STG_B (A_B + B_B)
#define GEMM_SMEM (NSTAGE * STG_B)

__global__ __launch_bounds__(256, 1) void gemm_mma(
    const __half* __restrict__ Ah, const __half* __restrict__ Bh,
    const float* __restrict__ bias, float* __restrict__ out,
    int N, int mode) {
    extern __shared__ __align__(16) char gsm[];
    const uint32_t s_base = s2u(gsm);

    const int tid = threadIdx.x;
    const int wid = tid >> 5, lane = tid & 31;
    const int warp_m = wid & 1, warp_n = wid >> 1;     // 2 x 4 warps of 64x64
    const int m0 = blockIdx.y * 128, n0 = blockIdx.x * 256;

    float acc[4][8][4];
#pragma unroll
    for (int mi = 0; mi < 4; mi++)
#pragma unroll
        for (int ni = 0; ni < 8; ni++)
#pragma unroll
            for (int c = 0; c < 4; c++) acc[mi][ni][c] = 0.0f;

    const int lrow = tid >> 2;          // 0..63
    const int lcol = (tid & 3) * 16;
    const int gcol = (tid & 3) * 8;

    const int a_row = warp_m * 64 + (lane & 15);
    const int a_kb = (lane >> 4) * 16;
    const int b_row_base = warp_n * 64 + (lane & 7) + ((lane & 16) ? 8 : 0);
    const int b_kb = (lane & 8) ? 16 : 0;

    // loader: A 512 chunks (2/thread), B 1024 chunks (4/thread)
#define GLOAD(sa, k0)                                                            \
    do {                                                                         \
        _Pragma("unroll")                                                        \
        for (int i = 0; i < 2; i++) {                                            \
            const int r = lrow + i * 64;                                         \
            cpa16((sa) + r * 80 + lcol, Ah + (size_t)(m0 + r) * 1024 + (k0) + gcol); \
        }                                                                        \
        _Pragma("unroll")                                                        \
        for (int i = 0; i < 4; i++) {                                            \
            const int r = lrow + i * 64;                                         \
            cpa16((sa) + A_B + r * 80 + lcol, Bh + (size_t)(n0 + r) * 1024 + (k0) + gcol); \
        }                                                                        \
    } while (0)

    // prologue: stages 0..2
#pragma unroll
    for (int s = 0; s < NSTAGE - 1; s++) {
        GLOAD(s_base + s * STG_B, s * 32);
        asm volatile("cp.async.commit_group;");
    }

    uint32_t af[2][4][4];
    uint32_t bf[2][8][2];

#define LOADF(fi, saddr, kb)                                                    \
    do {                                                                        \
        const uint32_t _sa = (saddr);                                           \
        const uint32_t _sb = _sa + A_B;                                         \
        _Pragma("unroll")                                                       \
        for (int mi = 0; mi < 4; mi++)                                          \
            ldm4(af[fi][mi], _sa + (a_row + mi * 16) * 80 + (kb) + a_kb);       \
        _Pragma("unroll")                                                       \
        for (int ni2 = 0; ni2 < 4; ni2++) {                                     \
            uint32_t _r[4];                                                     \
            ldm4(_r, _sb + (b_row_base + ni2 * 16) * 80 + (kb) + b_kb);         \
            bf[fi][ni2 * 2 + 0][0] = _r[0]; bf[fi][ni2 * 2 + 0][1] = _r[1];     \
            bf[fi][ni2 * 2 + 1][0] = _r[2]; bf[fi][ni2 * 2 + 1][1] = _r[3];     \
        }                                                                       \
    } while (0)

#define MMAALL(fi)                                                              \
    do {                                                                        \
        _Pragma("unroll")                                                       \
        for (int mi = 0; mi < 4; mi++)                                          \
            _Pragma("unroll")                                                   \
            for (int ni = 0; ni < 8; ni++)                                      \
                mma16816(acc[mi][ni], af[fi][mi], bf[fi][ni]);                  \
    } while (0)

    asm volatile("cp.async.wait_group %0;" :: "n"(NSTAGE - 2));
    __syncthreads();
    LOADF(0, s_base, 0);

#pragma unroll 1
    for (int kc = 0; kc < 32; kc++) {
        const uint32_t scur = s_base + (kc & (NSTAGE - 1)) * STG_B;

        LOADF(1, scur, 32);

        if (kc + NSTAGE - 1 < 32) {
            const int s = (kc + NSTAGE - 1) & (NSTAGE - 1);
            GLOAD(s_base + s * STG_B, (kc + NSTAGE - 1) * 32);
        }
        asm volatile("cp.async.commit_group;");

        MMAALL(0);

        if (kc < 31) {
            asm volatile("cp.async.wait_group %0;" :: "n"(NSTAGE - 2));
            __syncthreads();
            LOADF(0, s_base + ((kc + 1) & (NSTAGE - 1)) * STG_B, 0);
        }

        MMAALL(1);
    }
#undef GLOAD
#undef LOADF
#undef MMAALL

    const int rbase = warp_m * 64 + (lane >> 2);
    const int cbase = warp_n * 64 + (lane & 3) * 2;
#pragma unroll
    for (int mi = 0; mi < 4; mi++) {
#pragma unroll
        for (int ni = 0; ni < 8; ni++) {
            const int n = n0 + cbase + ni * 8;
            const float2 bsv = *reinterpret_cast<const float2*>(&bias[n]);
#pragma unroll
            for (int hh = 0; hh < 2; hh++) {
                const int m = m0 + rbase + mi * 16 + hh * 8;
                float vx = acc[mi][ni][hh * 2 + 0] + bsv.x;
                float vy = acc[mi][ni][hh * 2 + 1] + bsv.y;
                if (mode == 0) {
                    const int which = n >> 10;
                    const int ci = n & 1023;
                    const int h = ci >> 6, d = ci & 63;
                    const int b = m >> 11, t = m & 2047;
                    if (which == 0) { vx *= QSCALE; vy *= QSCALE; }
                    __half* dst = (which == 0) ? g_qh : (which == 1) ? g_kh : g_vh;
                    *reinterpret_cast<__half2*>(
                        &dst[(((size_t)b * Hz + h) * Tz + t) * HDz + d]) =
                        __floats2half2_rn(vx, vy);
                } else {
                    float2 v; v.x = vx; v.y = vy;
                    *reinterpret_cast<float2*>(&out[(size_t)m * N + n]) = v;
                }
            }
        }
    }
}

// ---------------- flash attention: mma.sync fp16 ------------------------------
#define ATT_SMEM 55296
#define KVSZ 9216

__global__ __launch_bounds__(128) void attn_mma() {
    extern __shared__ __align__(16) char sm[];
    const uint32_t sQ = s2u(sm);
    const uint32_t sK0 = sQ + 128 * 144;
    const uint32_t sV0 = sK0 + 2 * KVSZ;

    const int tid = threadIdx.x, lane = tid & 31, wid = tid >> 5;
    const int bh = blockIdx.y;
    const int q0 = ((int)gridDim.x - 1 - (int)blockIdx.x) * 128;

    const __half* qg = g_qh + ((size_t)bh * Tz + q0) * HDz;
    const __half* kg = g_kh + (size_t)bh * Tz * HDz;
    const __half* vg = g_vh + (size_t)bh * Tz * HDz;

    {
#pragma unroll
        for (int i = 0; i < 8; i++) {
            int idx = tid + i * 128, r = idx >> 3, ch = idx & 7;
            cpa16(sQ + r * 144 + ch * 16, qg + r * 64 + ch * 8);
        }
#pragma unroll
        for (int i = 0; i < 4; i++) {
            int idx = tid + i * 128, r = idx >> 3, ch = idx & 7;
            cpa16(sK0 + r * 144 + ch * 16, kg + r * 64 + ch * 8);
            cpa16(sV0 + r * 144 + ch * 16, vg + r * 64 + ch * 8);
        }
        asm volatile("cp.async.commit_group;");
    }

    float accO[2][8][4];
#pragma unroll
    for (int mi = 0; mi < 2; mi++)
#pragma unroll
        for (int ni = 0; ni < 8; ni++)
#pragma unroll
            for (int c = 0; c < 4; c++) accO[mi][ni][c] = 0.0f;
    float mrow[2][2] = { {-1e30f, -1e30f}, {-1e30f, -1e30f} };
    float lrow[2][2] = { {0.0f, 0.0f}, {0.0f, 0.0f} };

    const int qrow_b = wid * 32 + (lane & 15);
    const int q_kb = (lane >> 4) * 16;
    const int k_row = (lane & 7) + ((lane & 16) ? 8 : 0);
    const int k_kb = (lane & 8) ? 16 : 0;
    const int v_row = (lane & 7) + ((lane & 8) ? 8 : 0);
    const int v_cb = (lane & 16) ? 16 : 0;

    const int ntiles = (q0 >> 6) + 2;

#pragma unroll 1
    for (int kt = 0; kt < ntiles; kt++) {
        const int buf = kt & 1;
        if (kt < ntiles - 1) {
            const int nb = buf ^ 1;
            const __half* kgn = kg + (size_t)(kt + 1) * 64 * 64;
            const __half* vgn = vg + (size_t)(kt + 1) * 64 * 64;
#pragma unroll
            for (int i = 0; i < 4; i++) {
                int idx = tid + i * 128, r = idx >> 3, ch = idx & 7;
                cpa16(sK0 + nb * KVSZ + r * 144 + ch * 16, kgn + r * 64 + ch * 8);
                cpa16(sV0 + nb * KVSZ + r * 144 + ch * 16, vgn + r * 64 + ch * 8);
            }
            asm volatile("cp.async.commit_group;");
            asm volatile("cp.async.wait_group 1;");
        } else {
            asm volatile("cp.async.wait_group 0;");
        }
        __syncthreads();

        const uint32_t sk = sK0 + buf * KVSZ;
        const uint32_t sv = sV0 + buf * KVSZ;

        float accS[2][8][4];
#pragma unroll
        for (int mi = 0; mi < 2; mi++)
#pragma unroll
            for (int ni = 0; ni < 8; ni++)
#pragma unroll
                for (int c = 0; c < 4; c++) accS[mi][ni][c] = 0.0f;

#pragma unroll
        for (int ks = 0; ks < 4; ks++) {
            uint32_t qa[2][4];
#pragma unroll
            for (int mi = 0; mi < 2; mi++)
                ldm4(qa[mi], sQ + (qrow_b + mi * 16) * 144 + ks * 32 + q_kb);
            uint32_t kb[8][2];
#pragma unroll
            for (int ni2 = 0; ni2 < 4; ni2++) {
                uint32_t r[4];
                ldm4(r, sk + (k_row + ni2 * 16) * 144 + ks * 32 + k_kb);
                kb[ni2 * 2 + 0][0] = r[0]; kb[ni2 * 2 + 0][1] = r[1];
                kb[ni2 * 2 + 1][0] = r[2]; kb[ni2 * 2 + 1][1] = r[3];
            }
#pragma unroll
            for (int mi = 0; mi < 2; mi++)
#pragma unroll
                for (int ni = 0; ni < 8; ni++)
                    mma16816(accS[mi][ni], qa[mi], kb[ni]);
        }

        const int k0 = kt * 64;
        if (k0 + 63 > q0) {
            const int row0 = q0 + wid * 32 + (lane >> 2);
            const int colb = k0 + (lane & 3) * 2;
#pragma unroll
            for (int mi = 0; mi < 2; mi++)
#pragma unroll
                for (int ni = 0; ni < 8; ni++) {
                    const int kkb = colb + ni * 8;
                    const int rlo = row0 + mi * 16, rhi = rlo + 8;
                    if (kkb > rlo)     accS[mi][ni][0] = -1e30f;
                    if (kkb + 1 > rlo) accS[mi][ni][1] = -1e30f;
                    if (kkb > rhi)     accS[mi][ni][2] = -1e30f;
                    if (kkb + 1 > rhi) accS[mi][ni][3] = -1e30f;
                }
        }

#pragma unroll
        for (int mi = 0; mi < 2; mi++) {
            float mx0 = -1e30f, mx1 = -1e30f;
#pragma unroll
            for (int ni = 0; ni < 8; ni++) {
                mx0 = fmaxf(mx0, fmaxf(accS[mi][ni][0], accS[mi][ni][1]));
                mx1 = fmaxf(mx1, fmaxf(accS[mi][ni][2], accS[mi][ni][3]));
            }
            mx0 = fmaxf(mx0, __shfl_xor_sync(0xffffffff, mx0, 1));
            mx0 = fmaxf(mx0, __shfl_xor_sync(0xffffffff, mx0, 2));
            mx1 = fmaxf(mx1, __shfl_xor_sync(0xffffffff, mx1, 1));
            mx1 = fmaxf(mx1, __shfl_xor_sync(0xffffffff, mx1, 2));

            const float mn0 = fmaxf(mrow[mi][0], mx0);
            const float mn1 = fmaxf(mrow[mi][1], mx1);
            const float cor0 = ex2f(mrow[mi][0] - mn0);
            const float cor1 = ex2f(mrow[mi][1] - mn1);
            mrow[mi][0] = mn0; mrow[mi][1] = mn1;

            float sum0 = 0.0f, sum1 = 0.0f;
#pragma unroll
            for (int ni = 0; ni < 8; ni++) {
                float p0 = ex2f(accS[mi][ni][0] - mn0);
                float p1 = ex2f(accS[mi][ni][1] - mn0);
                float p2 = ex2f(accS[mi][ni][2] - mn1);
                float p3 = ex2f(accS[mi][ni][3] - mn1);
                accS[mi][ni][0] = p0; accS[mi][ni][1] = p1;
                accS[mi][ni][2] = p2; accS[mi][ni][3] = p3;
                sum0 += p0 + p1; sum1 += p2 + p3;
                accO[mi][ni][0] *= cor0; accO[mi][ni][1] *= cor0;
                accO[mi][ni][2] *= cor1; accO[mi][ni][3] *= cor1;
            }
            sum0 += __shfl_xor_sync(0xffffffff, sum0, 1);
            sum0 += __shfl_xor_sync(0xffffffff, sum0, 2);
            sum1 += __shfl_xor_sync(0xffffffff, sum1, 1);
            sum1 += __shfl_xor_sync(0xffffffff, sum1, 2);
            lrow[mi][0] = lrow[mi][0] * cor0 + sum0;
            lrow[mi][1] = lrow[mi][1] * cor1 + sum1;
        }

#pragma unroll
        for (int ks = 0; ks < 4; ks++) {
            uint32_t vb[8][2];
#pragma unroll
            for (int ni2 = 0; ni2 < 4; ni2++) {
                uint32_t r[4];
                ldm4t(r, sv + (ks * 16 + v_row) * 144 + ni2 * 32 + v_cb);
                vb[ni2 * 2 + 0][0] = r[0]; vb[ni2 * 2 + 0][1] = r[1];
                vb[ni2 * 2 + 1][0] = r[2]; vb[ni2 * 2 + 1][1] = r[3];
            }
#pragma unroll
            for (int mi = 0; mi < 2; mi++) {
                uint32_t pa[4];
                __half2 t0 = __floats2half2_rn(accS[mi][2 * ks][0], accS[mi][2 * ks][1]);
                __half2 t1 = __floats2half2_rn(accS[mi][2 * ks][2], accS[mi][2 * ks][3]);
                __half2 t2 = __floats2half2_rn(accS[mi][2 * ks + 1][0], accS[mi][2 * ks + 1][1]);
                __half2 t3 = __floats2half2_rn(accS[mi][2 * ks + 1][2], accS[mi][2 * ks + 1][3]);
                pa[0] = *reinterpret_cast<uint32_t*>(&t0);
                pa[1] = *reinterpret_cast<uint32_t*>(&t1);
                pa[2] = *reinterpret_cast<uint32_t*>(&t2);
                pa[3] = *reinterpret_cast<uint32_t*>(&t3);
#pragma unroll
                for (int ni = 0; ni < 8; ni++)
                    mma16816(accO[mi][ni], pa, vb[ni]);
            }
        }
        __syncthreads();
    }

    const int b = bh >> 4, h = bh & 15;
#pragma unroll
    for (int mi = 0; mi < 2; mi++) {
        const float inv0 = 1.0f / lrow[mi][0];
        const float inv1 = 1.0f / lrow[mi][1];
        const int rlo = q0 + wid * 32 + mi * 16 + (lane >> 2);
#pragma unroll
        for (int ni = 0; ni < 8; ni++) {
            const int col = h * HDz + ni * 8 + (lane & 3) * 2;
            *reinterpret_cast<__half2*>(
                &g_att_h[((size_t)b * Tz + rlo) * Cz + col]) =
                __floats2half2_rn(accO[mi][ni][0] * inv0, accO[mi][ni][1] * inv0);
            *reinterpret_cast<__half2*>(
                &g_att_h[((size_t)b * Tz + rlo + 8) * Cz + col]) =
                __floats2half2_rn(accO[mi][ni][2] * inv1, accO[mi][ni][3] * inv1);
        }
    }
}

// ---------------------------------------------------------------------------
extern "C" void kernel_launch(void* const* d_in, const int* in_sizes, int n_in,
                              void* d_out, int out_size) {
    const float* x      = (const float*)d_in[0];
    const float* W_attn = (const float*)d_in[1];
    const float* b_attn = (const float*)d_in[2];
    const float* W_proj = (const float*)d_in[3];
    const float* b_proj = (const float*)d_in[4];
    float* out = (float*)d_out;
    (void)in_sizes; (void)n_in; (void)out_size;

    __half* xh;  cudaGetSymbolAddress((void**)&xh,  g_xh);
    __half* wat; cudaGetSymbolAddress((void**)&wat, g_wat);
    __half* wpt; cudaGetSymbolAddress((void**)&wpt, g_wpt);
    __half* ath; cudaGetSymbolAddress((void**)&ath, g_att_h);

    cudaFuncSetAttribute(gemm_mma, cudaFuncAttributeMaxDynamicSharedMemorySize, GEMM_SMEM);
    cudaFuncSetAttribute(attn_mma, cudaFuncAttributeMaxDynamicSharedMemorySize, ATT_SMEM);

    {
        int n4 = Mz * Cz / 4;
        conv_x_kernel<<<(n4 + 255) / 256, 256>>>((const float4*)x, (uint2*)xh, n4);
        dim3 g(3 * Cz / 32, Cz / 32);
        convT_kernel<<<g, dim3(32, 8)>>>(W_attn, wat, Cz, 3 * Cz);
        dim3 g2(Cz / 32, Cz / 32);
        convT_kernel<<<g2, dim3(32, 8)>>>(W_proj, wpt, Cz, Cz);
    }

    // QKV: M=8192, N=3072, CTA tile 128x256
    dim3 g1(3 * Cz / 256, Mz / 128);
    gemm_mma<<<g1, 256, GEMM_SMEM>>>(xh, wat, b_attn, nullptr, 3 * Cz, 0);

    dim3 g2(Tz / 128, Bz * Hz);
    attn_mma<<<g2, 128, ATT_SMEM>>>();

    // Proj: M=8192, N=1024
    dim3 g3(Cz / 256, Mz / 128);
    gemm_mma<<<g3, 256, GEMM_SMEM>>>(ath, wpt, b_proj, out, Cz, 1);
}